// round 14
// baseline (speedup 1.0000x reference)
#include <cuda_runtime.h>
#include <cuda_fp16.h>
#include <math.h>
#include <stdint.h>

// Problem constants
#define B_    4
#define N_    1024
#define C_    1024
#define H_    16
#define DH    64
#define DHID  4096
#define R_    (B_*N_)   // 4096 token rows

// ---------------- scratch (device globals: allocation-guard safe) ----------
__device__ __half g_h  [R_*C_];          // LN outputs (half)
__device__ __half g_qkv[R_*3*C_];        // qkv (half)
__device__ __half g_o  [R_*C_];          // attention output (half)
__device__ float  g_x1 [R_*C_];          // residual after attention (fp32)
__device__ __half g_u  [R_*DHID];        // MLP hidden (half), lnh in-place
// half weight copies (one contiguous block: wq | wp | w1 | w2)
__device__ __half g_w  [(3*C_*C_) + (C_*C_) + (DHID*C_) + (C_*DHID)];

// ---------------- PTX helpers ----------------------------------------------
__device__ __forceinline__ uint32_t smem_u32(const void* p){
    uint32_t a;
    asm("{ .reg .u64 t; cvta.to.shared.u64 t, %1; cvt.u32.u64 %0, t; }"
        : "=r"(a) : "l"(p));
    return a;
}
__device__ __forceinline__ void cp16(uint32_t dst, const void* src){
    asm volatile("cp.async.cg.shared.global [%0], [%1], 16;\n" :: "r"(dst), "l"(src));
}
__device__ __forceinline__ void cp_commit(){ asm volatile("cp.async.commit_group;\n"); }
template<int NN>
__device__ __forceinline__ void cp_wait(){ asm volatile("cp.async.wait_group %0;\n" :: "n"(NN)); }
__device__ __forceinline__ void mma_f16(float* d, const uint32_t* a, const uint32_t* b){
    asm volatile(
      "mma.sync.aligned.m16n8k16.row.col.f32.f16.f16.f32 "
      "{%0,%1,%2,%3}, {%4,%5,%6,%7}, {%8,%9}, {%0,%1,%2,%3};\n"
      : "+f"(d[0]), "+f"(d[1]), "+f"(d[2]), "+f"(d[3])
      : "r"(a[0]), "r"(a[1]), "r"(a[2]), "r"(a[3]), "r"(b[0]), "r"(b[1]));
}
__device__ __forceinline__ void ldsm4(uint32_t* r, uint32_t a){
    asm volatile("ldmatrix.sync.aligned.m8n8.x4.shared.b16 {%0,%1,%2,%3}, [%4];"
      : "=r"(r[0]), "=r"(r[1]), "=r"(r[2]), "=r"(r[3]) : "r"(a));
}
__device__ __forceinline__ void ldsm4t(uint32_t* r, uint32_t a){
    asm volatile("ldmatrix.sync.aligned.m8n8.x4.trans.shared.b16 {%0,%1,%2,%3}, [%4];"
      : "=r"(r[0]), "=r"(r[1]), "=r"(r[2]), "=r"(r[3]) : "r"(a));
}
// half2 exp2 (one MUFU op per 2 elements)
__device__ __forceinline__ uint32_t h2exp2_(uint32_t x){
    uint32_t r; asm("ex2.approx.f16x2 %0, %1;" : "=r"(r) : "r"(x)); return r;
}
__device__ __forceinline__ void store2(float* p, float a, float b){
    float2 t; t.x = a; t.y = b; *(float2*)p = t;
}
__device__ __forceinline__ void store2(__half* p, float a, float b){
    *(__half2*)p = __floats2half2_rn(a, b);
}

// ---------------- fused fp32 -> fp16 weight conversion ----------------------
__global__ void cvt_all_kernel(const float* __restrict__ s0,
                               const float* __restrict__ s1,
                               const float* __restrict__ s2,
                               const float* __restrict__ s3,
                               __half* __restrict__ dst)
{
    constexpr int N0 = 3*C_*C_/4;
    constexpr int N1 = C_*C_/4;
    constexpr int N2 = DHID*C_/4;
    constexpr int N3 = C_*DHID/4;
    int i = blockIdx.x * 256 + threadIdx.x;
    if (i >= N0 + N1 + N2 + N3) return;
    const float* src; int j = i;
    if      (j < N0)            { src = s0; }
    else if ((j -= N0) < N1)    { src = s1; }
    else if ((j -= N1) < N2)    { src = s2; }
    else    { j -= N2;            src = s3; }
    float4 v = ((const float4*)src)[j];
    __half2 h0 = __floats2half2_rn(v.x, v.y);
    __half2 h1 = __floats2half2_rn(v.z, v.w);
    uint2 r; r.x = *(uint32_t*)&h0; r.y = *(uint32_t*)&h1;
    ((uint2*)dst)[i] = r;
}

// ---------------- LayerNorm, warp-per-row (C=1024, fp32 in, half out) -------
__global__ void __launch_bounds__(256)
ln_warp(const float* __restrict__ x,
        const float* __restrict__ g,
        const float* __restrict__ bb,
        __half* __restrict__ y)
{
    const int warp = threadIdx.x >> 5, lane = threadIdx.x & 31;
    const int row  = blockIdx.x * 8 + warp;
    const float* xr = x + (size_t)row * C_;
    __half*      yr = y + (size_t)row * C_;

    float v[32];
    float s = 0.f, sq = 0.f;
    #pragma unroll
    for (int j = 0; j < 8; j++) {
        float4 t = *(const float4*)(xr + j * 128 + lane * 4);
        v[j*4+0] = t.x; v[j*4+1] = t.y; v[j*4+2] = t.z; v[j*4+3] = t.w;
        s  += t.x + t.y + t.z + t.w;
        sq += t.x*t.x + t.y*t.y + t.z*t.z + t.w*t.w;
    }
    #pragma unroll
    for (int o = 16; o > 0; o >>= 1) {
        s  += __shfl_xor_sync(0xffffffffu, s,  o);
        sq += __shfl_xor_sync(0xffffffffu, sq, o);
    }
    const float mu = s * (1.f / C_);
    const float r  = rsqrtf(sq * (1.f / C_) - mu * mu + 1e-5f);

    #pragma unroll
    for (int j = 0; j < 8; j++) {
        int idx = j * 128 + lane * 4;
        float4 gg = *(const float4*)(g  + idx);
        float4 be = *(const float4*)(bb + idx);
        float o0 = (v[j*4+0] - mu) * r * gg.x + be.x;
        float o1 = (v[j*4+1] - mu) * r * gg.y + be.y;
        float o2 = (v[j*4+2] - mu) * r * gg.z + be.z;
        float o3 = (v[j*4+3] - mu) * r * gg.w + be.w;
        __half2 h0 = __floats2half2_rn(o0, o1);
        __half2 h1 = __floats2half2_rn(o2, o3);
        uint2 out; out.x = *(uint32_t*)&h0; out.y = *(uint32_t*)&h1;
        *(uint2*)(yr + idx) = out;
    }
}

// ---------------- LayerNorm block-per-row (half in/out, DHID) ---------------
template<int CC>
__global__ void ln_h(const __half* __restrict__ x,
                     const float* __restrict__ g,
                     const float* __restrict__ bb,
                     __half* __restrict__ y)
{
    constexpr int PT = CC / 256;
    const int row = blockIdx.x;
    const int tid = threadIdx.x;
    const __half* xr = x + (size_t)row * CC;
    __half*       yr = y + (size_t)row * CC;

    float v[PT];
    float s = 0.f, sq = 0.f;
    #pragma unroll
    for (int i = 0; i < PT / 4; i++) {
        int idx = tid * 4 + i * 1024;
        uint2 raw = *(const uint2*)(xr + idx);
        __half2 h0 = *(__half2*)&raw.x, h1 = *(__half2*)&raw.y;
        float2 f0 = __half22float2(h0), f1 = __half22float2(h1);
        v[i*4+0] = f0.x; v[i*4+1] = f0.y; v[i*4+2] = f1.x; v[i*4+3] = f1.y;
        s  += f0.x + f0.y + f1.x + f1.y;
        sq += f0.x*f0.x + f0.y*f0.y + f1.x*f1.x + f1.y*f1.y;
    }
    #pragma unroll
    for (int o = 16; o > 0; o >>= 1) {
        s  += __shfl_xor_sync(0xffffffffu, s,  o);
        sq += __shfl_xor_sync(0xffffffffu, sq, o);
    }
    __shared__ float rs[8], rq[8], stats[2];
    int w = tid >> 5, ln = tid & 31;
    if (ln == 0) { rs[w] = s; rq[w] = sq; }
    __syncthreads();
    if (tid == 0) {
        float ts = 0.f, tq = 0.f;
        #pragma unroll
        for (int i = 0; i < 8; i++) { ts += rs[i]; tq += rq[i]; }
        float mu  = ts / (float)CC;
        float var = tq / (float)CC - mu * mu;
        stats[0] = mu;
        stats[1] = rsqrtf(var + 1e-5f);
    }
    __syncthreads();
    float mu = stats[0], r = stats[1];
    #pragma unroll
    for (int i = 0; i < PT / 4; i++) {
        int idx = tid * 4 + i * 1024;
        float4 gg = *(const float4*)(g  + idx);
        float4 be = *(const float4*)(bb + idx);
        float o0 = (v[i*4+0] - mu) * r * gg.x + be.x;
        float o1 = (v[i*4+1] - mu) * r * gg.y + be.y;
        float o2 = (v[i*4+2] - mu) * r * gg.z + be.z;
        float o3 = (v[i*4+3] - mu) * r * gg.w + be.w;
        __half2 h0 = __floats2half2_rn(o0, o1);
        __half2 h1 = __floats2half2_rn(o2, o3);
        uint2 out; out.x = *(uint32_t*)&h0; out.y = *(uint32_t*)&h1;
        *(uint2*)(yr + idx) = out;
    }
}

// ---------------- FP16 tensor-core GEMM (NT): C = A[M,K] @ B[N,K]^T ---------
// 128x128x64 tiles, 3-stage cp.async, XOR-swizzled smem, ldmatrix with
// register double-buffered fragments (LDSM latency hidden behind MMAs).
template<int EPI, typename TO>
__global__ void __launch_bounds__(256, 2)
gemm_h(const __half* __restrict__ A, const __half* __restrict__ Bm,
       TO* __restrict__ Cc, const float* __restrict__ bias,
       const float* __restrict__ res, int M, int Nn, int K)
{
    constexpr int BM = 128, BN = 128, BK = 64, ST = 3;
    constexpr int STAGE_H = BM * BK;
    extern __shared__ char smc[];
    __half* As = (__half*)smc;
    __half* Bs = As + ST * STAGE_H;

    const int tid  = threadIdx.x;
    const int warp = tid >> 5, lane = tid & 31;
    const int g    = lane >> 2, qd = lane & 3;
    const int wM   = warp >> 2, wN = warp & 3;
    const int bM   = blockIdx.y * BM, bN = blockIdx.x * BN;

    const uint32_t as_u = smem_u32(As);
    const uint32_t bs_u = smem_u32(Bs);

    const int l7 = lane & 7;
    int aRow[4], bRow[2];
    #pragma unroll
    for (int i = 0; i < 4; i++)
        aRow[i] = wM * 64 + i * 16 + l7 + ((lane >> 3) & 1) * 8;
    const int cA = (lane >> 4) & 1;
    #pragma unroll
    for (int jj = 0; jj < 2; jj++)
        bRow[jj] = wN * 32 + jj * 16 + l7 + ((lane >> 4) & 1) * 8;
    const int cB = (lane >> 3) & 1;

    float acc[4][4][4];
    #pragma unroll
    for (int i = 0; i < 4; i++)
        #pragma unroll
        for (int j = 0; j < 4; j++)
            #pragma unroll
            for (int e = 0; e < 4; e++) acc[i][j][e] = 0.f;

    const int KT = K / BK;

    auto load_stage = [&](int s, int k0) {
        #pragma unroll
        for (int j = 0; j < 4; j++) {
            int f = tid + j * 256;
            int r = f >> 3, q = f & 7;
            uint32_t off = (uint32_t)(r * 128 + ((q ^ (r & 7)) * 16));
            cp16(as_u + (uint32_t)s * 16384u + off,
                 A  + (size_t)(bM + r) * K + k0 + q * 8);
            cp16(bs_u + (uint32_t)s * 16384u + off,
                 Bm + (size_t)(bN + r) * K + k0 + q * 8);
        }
        cp_commit();
    };

    #pragma unroll
    for (int s = 0; s < ST - 1; s++) load_stage(s, s * BK);

    for (int t = 0; t < KT; t++) {
        cp_wait<ST - 2>();
        __syncthreads();

        int tn = t + ST - 1;
        if (tn < KT) load_stage(tn % ST, tn * BK);
        else         cp_commit();

        const uint32_t a_st = as_u + (uint32_t)(t % ST) * 16384u;
        const uint32_t b_st = bs_u + (uint32_t)(t % ST) * 16384u;

        // register double-buffered fragments: prefetch one fragment ahead
        uint32_t afb[2][4];     // A fragment ring  (fi = kk*4 + i)
        uint32_t bfb[2][2][4];  // B fragment ring  (per kk)

        auto ldA = [&](uint32_t* dst, int fi){
            int kk = fi >> 2, i = fi & 3;
            int ch = 2 * kk + cA;
            ldsm4(dst, a_st + (uint32_t)(aRow[i] * 128
                       + ((ch ^ (aRow[i] & 7)) * 16)));
        };
        auto ldB = [&](uint32_t (*dst)[4], int kk){
            int ch = 2 * kk + cB;
            #pragma unroll
            for (int jj = 0; jj < 2; jj++)
                ldsm4(dst[jj], b_st + (uint32_t)(bRow[jj] * 128
                           + ((ch ^ (bRow[jj] & 7)) * 16)));
        };

        ldB(bfb[0], 0);
        ldA(afb[0], 0);

        #pragma unroll
        for (int fi = 0; fi < 16; fi++) {
            const int kk  = fi >> 2;
            const int i   = fi & 3;
            const int ac  = fi & 1;
            const int bc  = kk & 1;
            if (i == 0 && kk < 3) ldB(bfb[bc ^ 1], kk + 1);
            if (fi < 15)          ldA(afb[ac ^ 1], fi + 1);
            #pragma unroll
            for (int j = 0; j < 4; j++)
                mma_f16(acc[i][j], afb[ac], &bfb[bc][j >> 1][(j & 1) * 2]);
        }
    }

    #pragma unroll
    for (int i = 0; i < 4; i++) {
        #pragma unroll
        for (int j = 0; j < 4; j++) {
            int r0 = bM + wM * 64 + i * 16 + g;
            int c0 = bN + wN * 32 + j * 8 + qd * 2;
            #pragma unroll
            for (int hh = 0; hh < 2; hh++) {
                int r = r0 + hh * 8;
                float v0 = acc[i][j][hh * 2 + 0];
                float v1 = acc[i][j][hh * 2 + 1];
                if (EPI >= 1) { v0 += bias[c0]; v1 += bias[c0 + 1]; }
                if (EPI == 1) {
                    v0 = 0.5f * v0 * (1.f + erff(v0 * 0.70710678118654752f));
                    v1 = 0.5f * v1 * (1.f + erff(v1 * 0.70710678118654752f));
                }
                if (EPI == 2) {
                    const float2 rr = *(const float2*)(res + (size_t)r * Nn + c0);
                    v0 += rr.x; v1 += rr.y;
                }
                store2(Cc + (size_t)r * Nn + c0, v0, v1);
            }
        }
    }
}

// ---------------- FP16 tensor-core flash attention (persistent) --------------
#define AGRID 296
__global__ void __launch_bounds__(256, 2)
attn_mma(const __half* __restrict__ qkv, __half* __restrict__ o)
{
    extern __shared__ char smc[];
    const uint32_t sb   = smem_u32(smc);
    const uint32_t ks_u = sb;
    const uint32_t vs_u = sb + 16384;
    const uint32_t qs_u = sb + 32768;
    __half* Qs = (__half*)(smc + 32768);

    const int tid  = threadIdx.x;
    const int warp = tid >> 5, lane = tid & 31;
    const int l7   = lane & 7;
    const int g    = lane >> 2, qd = lane & 3;
    const int wr   = warp * 16;
    const int RS = 3 * C_;
    const int NT = N_ / 64;

    const int kRow = l7 + ((lane >> 4) & 1) * 8;
    const int kCh  = (lane >> 3) & 1;
    const int vRow = l7 + ((lane >> 3) & 1) * 8;
    const int vCh  = (lane >> 4) & 1;
    const int qrow = wr + l7 + ((lane >> 3) & 1) * 8;
    const int qch  = (lane >> 4) & 1;
    const __half2 sc = __float2half2_rn(0.125f * 1.44269504088896340736f);

    for (int item = blockIdx.x; item < 512; item += AGRID) {
        const int b  = item >> 7;
        const int h  = (item >> 3) & 15;
        const int q0 = (item & 7) * 128;

        auto prefetch = [&](int t) {
            #pragma unroll
            for (int e = 0; e < 2; e++) {
                int f = tid + e * 256;
                int r = f >> 3, q = f & 7;
                uint32_t off = (uint32_t)((t & 1) * 8192 + r * 128 + ((q ^ (r & 7)) * 16));
                const __half* base = qkv + (size_t)(b * N_ + t * 64 + r) * RS + h * DH + q * 8;
                cp16(ks_u + off, base + C_);
                cp16(vs_u + off, base + 2 * C_);
            }
            cp_commit();
        };
        prefetch(0);

        for (int i = tid; i < 128 * 8; i += 256) {
            int r = i >> 3, c = i & 7;
            *(uint4*)&Qs[r * 72 + c * 8] =
                *(const uint4*)(qkv + (size_t)(b * N_ + q0 + r) * RS + h * DH + c * 8);
        }
        __syncthreads();

        uint32_t qf[4][4];
        #pragma unroll
        for (int kk = 0; kk < 4; kk++) {
            ldsm4(qf[kk], qs_u + (uint32_t)(qrow * 144 + (2 * kk + qch) * 16));
            #pragma unroll
            for (int e = 0; e < 4; e++) {
                __half2 t = __hmul2(*(__half2*)&qf[kk][e], sc);
                qf[kk][e] = *(uint32_t*)&t;
            }
        }

        float oacc[8][4];
        #pragma unroll
        for (int nb = 0; nb < 8; nb++)
            #pragma unroll
            for (int e = 0; e < 4; e++) oacc[nb][e] = 0.f;
        float m0 = -1e30f, m1 = -1e30f, l0 = 0.f, l1 = 0.f;

        for (int t = 0; t < NT; t++) {
            cp_wait<0>();
            __syncthreads();
            if (t + 1 < NT) prefetch(t + 1);

            const uint32_t K_ = ks_u + (uint32_t)((t & 1) * 8192);
            const uint32_t V_ = vs_u + (uint32_t)((t & 1) * 8192);

            // S = (Q * 0.125 * log2e) @ K^T
            float sacc[8][4];
            #pragma unroll
            for (int nb = 0; nb < 8; nb++)
                #pragma unroll
                for (int e = 0; e < 4; e++) sacc[nb][e] = 0.f;
            #pragma unroll
            for (int kk = 0; kk < 4; kk++) {
                uint32_t bf[4][4];
                #pragma unroll
                for (int p = 0; p < 4; p++) {
                    int row = p * 16 + kRow;
                    ldsm4(bf[p], K_ + (uint32_t)(row * 128
                                + (((2 * kk + kCh) ^ (row & 7)) * 16)));
                }
                #pragma unroll
                for (int nb = 0; nb < 8; nb++)
                    mma_f16(sacc[nb], qf[kk], &bf[nb >> 1][(nb & 1) * 2]);
            }

            // online softmax (exp2 domain), exp in f16x2, P = register fragments
            float mx0 = -1e30f, mx1 = -1e30f;
            #pragma unroll
            for (int nb = 0; nb < 8; nb++) {
                mx0 = fmaxf(mx0, fmaxf(sacc[nb][0], sacc[nb][1]));
                mx1 = fmaxf(mx1, fmaxf(sacc[nb][2], sacc[nb][3]));
            }
            mx0 = fmaxf(mx0, __shfl_xor_sync(0xffffffffu, mx0, 1));
            mx0 = fmaxf(mx0, __shfl_xor_sync(0xffffffffu, mx0, 2));
            mx1 = fmaxf(mx1, __shfl_xor_sync(0xffffffffu, mx1, 1));
            mx1 = fmaxf(mx1, __shfl_xor_sync(0xffffffffu, mx1, 2));

            float mn0 = fmaxf(m0, mx0), mn1 = fmaxf(m1, mx1);
            float cc0 = exp2f(m0 - mn0), cc1 = exp2f(m1 - mn1);
            float s0 = 0.f, s1 = 0.f;
            uint32_t pa[8], pb[8];
            #pragma unroll
            for (int nb = 0; nb < 8; nb++) {
                __half2 da = __floats2half2_rn(sacc[nb][0] - mn0, sacc[nb][1] - mn0);
                __half2 db = __floats2half2_rn(sacc[nb][2] - mn1, sacc[nb][3] - mn1);
                pa[nb] = h2exp2_(*(uint32_t*)&da);
                pb[nb] = h2exp2_(*(uint32_t*)&db);
                float2 fa = __half22float2(*(__half2*)&pa[nb]);
                float2 fb = __half22float2(*(__half2*)&pb[nb]);
                s0 += fa.x + fa.y;
                s1 += fb.x + fb.y;
            }
            s0 += __shfl_xor_sync(0xffffffffu, s0, 1);
            s0 += __shfl_xor_sync(0xffffffffu, s0, 2);
            s1 += __shfl_xor_sync(0xffffffffu, s1, 1);
            s1 += __shfl_xor_sync(0xffffffffu, s1, 2);
            l0 = l0 * cc0 + s0;  l1 = l1 * cc1 + s1;
            m0 = mn0;  m1 = mn1;
            #pragma unroll
            for (int nb = 0; nb < 8; nb++) {
                oacc[nb][0] *= cc0; oacc[nb][1] *= cc0;
                oacc[nb][2] *= cc1; oacc[nb][3] *= cc1;
            }

            // O += P @ V
            #pragma unroll
            for (int jc = 0; jc < 4; jc++) {
                uint32_t af[4];
                af[0] = pa[2 * jc];     af[1] = pb[2 * jc];
                af[2] = pa[2 * jc + 1]; af[3] = pb[2 * jc + 1];
                uint32_t bf[4][4];
                #pragma unroll
                for (int p = 0; p < 4; p++) {
                    int row = jc * 16 + vRow;
                    ldsm4t(bf[p], V_ + (uint32_t)(row * 128
                                 + (((2 * p + vCh) ^ (row & 7)) * 16)));
                }
                #pragma unroll
                for (int nb = 0; nb < 8; nb++)
                    mma_f16(oacc[nb], af, &bf[nb >> 1][(nb & 1) * 2]);
            }
        }

        float i0 = 1.f / l0, i1 = 1.f / l1;
        __half* op0 = o + (size_t)(b * N_ + q0 + wr + g    ) * C_ + h * DH;
        __half* op1 = o + (size_t)(b * N_ + q0 + wr + g + 8) * C_ + h * DH;
        #pragma unroll
        for (int nb = 0; nb < 8; nb++) {
            int c = nb * 8 + qd * 2;
            *(__half2*)(op0 + c) = __floats2half2_rn(oacc[nb][0] * i0, oacc[nb][1] * i0);
            *(__half2*)(op1 + c) = __floats2half2_rn(oacc[nb][2] * i1, oacc[nb][3] * i1);
        }
    }
}

// ---------------- launch ----------------------------------------------------
extern "C" void kernel_launch(void* const* d_in, const int* in_sizes, int n_in,
                              void* d_out, int out_size)
{
    const float* x      = (const float*)d_in[0];
    const float* qkv_w  = (const float*)d_in[1];
    const float* proj_w = (const float*)d_in[2];
    const float* proj_b = (const float*)d_in[3];
    const float* fc1_w  = (const float*)d_in[4];
    const float* fc1_b  = (const float*)d_in[5];
    const float* fc2_w  = (const float*)d_in[6];
    const float* fc2_b  = (const float*)d_in[7];
    const float* ln1_g  = (const float*)d_in[8];
    const float* ln1_b  = (const float*)d_in[9];
    const float* ln2_g  = (const float*)d_in[10];
    const float* ln2_b  = (const float*)d_in[11];
    const float* lnh_g  = (const float*)d_in[12];
    const float* lnh_b  = (const float*)d_in[13];
    float* out = (float*)d_out;

    __half *h, *qkv, *o, *u, *w;
    float *x1;
    cudaGetSymbolAddress((void**)&h,   g_h);
    cudaGetSymbolAddress((void**)&qkv, g_qkv);
    cudaGetSymbolAddress((void**)&o,   g_o);
    cudaGetSymbolAddress((void**)&x1,  g_x1);
    cudaGetSymbolAddress((void**)&u,   g_u);
    cudaGetSymbolAddress((void**)&w,   g_w);
    __half* wq = w;
    __half* wp = wq + 3*C_*C_;
    __half* w1 = wp + C_*C_;
    __half* w2 = w1 + DHID*C_;

    const int SMEM  = 3 * 128 * 64 * 2 * 2;          // 96 KB (GEMM)
    const int ASMEM = 16384 + 16384 + 128 * 72 * 2;  // 50.5 KB (attention)
    cudaFuncSetAttribute(gemm_h<0,__half>, cudaFuncAttributeMaxDynamicSharedMemorySize, SMEM);
    cudaFuncSetAttribute(gemm_h<1,__half>, cudaFuncAttributeMaxDynamicSharedMemorySize, SMEM);
    cudaFuncSetAttribute(gemm_h<2,float >, cudaFuncAttributeMaxDynamicSharedMemorySize, SMEM);
    cudaFuncSetAttribute(attn_mma,         cudaFuncAttributeMaxDynamicSharedMemorySize, ASMEM);

    // fused weight conversion fp32 -> fp16 (one launch)
    {
        const int total4 = (3*C_*C_ + C_*C_ + DHID*C_ + C_*DHID) / 4;
        cvt_all_kernel<<<(total4 + 255)/256, 256>>>(qkv_w, proj_w, fc1_w, fc2_w, w);
    }

    // --- attention sublayer ---
    ln_warp<<<R_/8, 256>>>(x, ln1_g, ln1_b, h);
    gemm_h<0,__half><<<dim3(3*C_/128, R_/128), 256, SMEM>>>(h, wq, qkv,
                                                   nullptr, nullptr, R_, 3*C_, C_);
    attn_mma<<<AGRID, 256, ASMEM>>>(qkv, o);
    gemm_h<2,float><<<dim3(C_/128, R_/128), 256, SMEM>>>(o, wp, x1,
                                                   proj_b, x, R_, C_, C_);

    // --- MLP sublayer ---
    ln_warp<<<R_/8, 256>>>(x1, ln2_g, ln2_b, h);
    gemm_h<1,__half><<<dim3(DHID/128, R_/128), 256, SMEM>>>(h, w1, u,
                                                   fc1_b, nullptr, R_, DHID, C_);
    ln_h<DHID><<<R_, 256>>>(u, lnh_g, lnh_b, u);
    gemm_h<2,float><<<dim3(C_/128, R_/128), 256, SMEM>>>(u, w2, out,
                                                   fc2_b, x1, R_, C_, DHID);
}

// round 15
// speedup vs baseline: 1.0197x; 1.0197x over previous
#include <cuda_runtime.h>
#include <cuda_fp16.h>
#include <math.h>
#include <stdint.h>

// Problem constants
#define B_    4
#define N_    1024
#define C_    1024
#define H_    16
#define DH    64
#define DHID  4096
#define R_    (B_*N_)   // 4096 token rows

// ---------------- scratch (device globals: allocation-guard safe) ----------
__device__ __half g_h  [R_*C_];          // LN outputs (half)
__device__ __half g_qkv[R_*3*C_];        // qkv (half)
__device__ __half g_o  [R_*C_];          // attention output (half)
__device__ float  g_x1 [R_*C_];          // residual after attention (fp32)
__device__ __half g_u  [R_*DHID];        // MLP hidden (half), lnh in-place
// half weight copies (one contiguous block: wq | wp | w1 | w2)
__device__ __half g_w  [(3*C_*C_) + (C_*C_) + (DHID*C_) + (C_*DHID)];

// ---------------- PTX helpers ----------------------------------------------
__device__ __forceinline__ uint32_t smem_u32(const void* p){
    uint32_t a;
    asm("{ .reg .u64 t; cvta.to.shared.u64 t, %1; cvt.u32.u64 %0, t; }"
        : "=r"(a) : "l"(p));
    return a;
}
__device__ __forceinline__ void cp16(uint32_t dst, const void* src){
    asm volatile("cp.async.cg.shared.global [%0], [%1], 16;\n" :: "r"(dst), "l"(src));
}
__device__ __forceinline__ void cp_commit(){ asm volatile("cp.async.commit_group;\n"); }
template<int NN>
__device__ __forceinline__ void cp_wait(){ asm volatile("cp.async.wait_group %0;\n" :: "n"(NN)); }
__device__ __forceinline__ void mma_f16(float* d, const uint32_t* a, const uint32_t* b){
    asm volatile(
      "mma.sync.aligned.m16n8k16.row.col.f32.f16.f16.f32 "
      "{%0,%1,%2,%3}, {%4,%5,%6,%7}, {%8,%9}, {%0,%1,%2,%3};\n"
      : "+f"(d[0]), "+f"(d[1]), "+f"(d[2]), "+f"(d[3])
      : "r"(a[0]), "r"(a[1]), "r"(a[2]), "r"(a[3]), "r"(b[0]), "r"(b[1]));
}
__device__ __forceinline__ void ldsm4(uint32_t* r, uint32_t a){
    asm volatile("ldmatrix.sync.aligned.m8n8.x4.shared.b16 {%0,%1,%2,%3}, [%4];"
      : "=r"(r[0]), "=r"(r[1]), "=r"(r[2]), "=r"(r[3]) : "r"(a));
}
__device__ __forceinline__ void ldsm4t(uint32_t* r, uint32_t a){
    asm volatile("ldmatrix.sync.aligned.m8n8.x4.trans.shared.b16 {%0,%1,%2,%3}, [%4];"
      : "=r"(r[0]), "=r"(r[1]), "=r"(r[2]), "=r"(r[3]) : "r"(a));
}
// half2 exp2 (one MUFU op per 2 elements)
__device__ __forceinline__ uint32_t h2exp2_(uint32_t x){
    uint32_t r; asm("ex2.approx.f16x2 %0, %1;" : "=r"(r) : "r"(x)); return r;
}
__device__ __forceinline__ void store2(float* p, float a, float b){
    float2 t; t.x = a; t.y = b; *(float2*)p = t;
}
__device__ __forceinline__ void store2(__half* p, float a, float b){
    *(__half2*)p = __floats2half2_rn(a, b);
}

// ---------------- fused fp32 -> fp16 weight conversion ----------------------
__global__ void cvt_all_kernel(const float* __restrict__ s0,
                               const float* __restrict__ s1,
                               const float* __restrict__ s2,
                               const float* __restrict__ s3,
                               __half* __restrict__ dst)
{
    constexpr int N0 = 3*C_*C_/4;
    constexpr int N1 = C_*C_/4;
    constexpr int N2 = DHID*C_/4;
    constexpr int N3 = C_*DHID/4;
    int i = blockIdx.x * 256 + threadIdx.x;
    if (i >= N0 + N1 + N2 + N3) return;
    const float* src; int j = i;
    if      (j < N0)            { src = s0; }
    else if ((j -= N0) < N1)    { src = s1; }
    else if ((j -= N1) < N2)    { src = s2; }
    else    { j -= N2;            src = s3; }
    float4 v = ((const float4*)src)[j];
    __half2 h0 = __floats2half2_rn(v.x, v.y);
    __half2 h1 = __floats2half2_rn(v.z, v.w);
    uint2 r; r.x = *(uint32_t*)&h0; r.y = *(uint32_t*)&h1;
    ((uint2*)dst)[i] = r;
}

// ---------------- LayerNorm, warp-per-row (C=1024, fp32 in, half out) -------
__global__ void __launch_bounds__(256)
ln_warp(const float* __restrict__ x,
        const float* __restrict__ g,
        const float* __restrict__ bb,
        __half* __restrict__ y)
{
    const int warp = threadIdx.x >> 5, lane = threadIdx.x & 31;
    const int row  = blockIdx.x * 8 + warp;
    const float* xr = x + (size_t)row * C_;
    __half*      yr = y + (size_t)row * C_;

    float v[32];
    float s = 0.f, sq = 0.f;
    #pragma unroll
    for (int j = 0; j < 8; j++) {
        float4 t = *(const float4*)(xr + j * 128 + lane * 4);
        v[j*4+0] = t.x; v[j*4+1] = t.y; v[j*4+2] = t.z; v[j*4+3] = t.w;
        s  += t.x + t.y + t.z + t.w;
        sq += t.x*t.x + t.y*t.y + t.z*t.z + t.w*t.w;
    }
    #pragma unroll
    for (int o = 16; o > 0; o >>= 1) {
        s  += __shfl_xor_sync(0xffffffffu, s,  o);
        sq += __shfl_xor_sync(0xffffffffu, sq, o);
    }
    const float mu = s * (1.f / C_);
    const float r  = rsqrtf(sq * (1.f / C_) - mu * mu + 1e-5f);

    #pragma unroll
    for (int j = 0; j < 8; j++) {
        int idx = j * 128 + lane * 4;
        float4 gg = *(const float4*)(g  + idx);
        float4 be = *(const float4*)(bb + idx);
        float o0 = (v[j*4+0] - mu) * r * gg.x + be.x;
        float o1 = (v[j*4+1] - mu) * r * gg.y + be.y;
        float o2 = (v[j*4+2] - mu) * r * gg.z + be.z;
        float o3 = (v[j*4+3] - mu) * r * gg.w + be.w;
        __half2 h0 = __floats2half2_rn(o0, o1);
        __half2 h1 = __floats2half2_rn(o2, o3);
        uint2 out; out.x = *(uint32_t*)&h0; out.y = *(uint32_t*)&h1;
        *(uint2*)(yr + idx) = out;
    }
}

// ---------------- LayerNorm block-per-row (half in/out, DHID) ---------------
template<int CC>
__global__ void ln_h(const __half* __restrict__ x,
                     const float* __restrict__ g,
                     const float* __restrict__ bb,
                     __half* __restrict__ y)
{
    constexpr int PT = CC / 256;
    const int row = blockIdx.x;
    const int tid = threadIdx.x;
    const __half* xr = x + (size_t)row * CC;
    __half*       yr = y + (size_t)row * CC;

    float v[PT];
    float s = 0.f, sq = 0.f;
    #pragma unroll
    for (int i = 0; i < PT / 4; i++) {
        int idx = tid * 4 + i * 1024;
        uint2 raw = *(const uint2*)(xr + idx);
        __half2 h0 = *(__half2*)&raw.x, h1 = *(__half2*)&raw.y;
        float2 f0 = __half22float2(h0), f1 = __half22float2(h1);
        v[i*4+0] = f0.x; v[i*4+1] = f0.y; v[i*4+2] = f1.x; v[i*4+3] = f1.y;
        s  += f0.x + f0.y + f1.x + f1.y;
        sq += f0.x*f0.x + f0.y*f0.y + f1.x*f1.x + f1.y*f1.y;
    }
    #pragma unroll
    for (int o = 16; o > 0; o >>= 1) {
        s  += __shfl_xor_sync(0xffffffffu, s,  o);
        sq += __shfl_xor_sync(0xffffffffu, sq, o);
    }
    __shared__ float rs[8], rq[8], stats[2];
    int w = tid >> 5, ln = tid & 31;
    if (ln == 0) { rs[w] = s; rq[w] = sq; }
    __syncthreads();
    if (tid == 0) {
        float ts = 0.f, tq = 0.f;
        #pragma unroll
        for (int i = 0; i < 8; i++) { ts += rs[i]; tq += rq[i]; }
        float mu  = ts / (float)CC;
        float var = tq / (float)CC - mu * mu;
        stats[0] = mu;
        stats[1] = rsqrtf(var + 1e-5f);
    }
    __syncthreads();
    float mu = stats[0], r = stats[1];
    #pragma unroll
    for (int i = 0; i < PT / 4; i++) {
        int idx = tid * 4 + i * 1024;
        float4 gg = *(const float4*)(g  + idx);
        float4 be = *(const float4*)(bb + idx);
        float o0 = (v[i*4+0] - mu) * r * gg.x + be.x;
        float o1 = (v[i*4+1] - mu) * r * gg.y + be.y;
        float o2 = (v[i*4+2] - mu) * r * gg.z + be.z;
        float o3 = (v[i*4+3] - mu) * r * gg.w + be.w;
        __half2 h0 = __floats2half2_rn(o0, o1);
        __half2 h1 = __floats2half2_rn(o2, o3);
        uint2 out; out.x = *(uint32_t*)&h0; out.y = *(uint32_t*)&h1;
        *(uint2*)(yr + idx) = out;
    }
}

// ---------------- FP16 tensor-core GEMM (NT): C = A[M,K] @ B[N,K]^T ---------
// R13 version: 128x128x64 tiles, 3-stage cp.async, XOR-swizzled smem,
// ldmatrix fragments, 2 CTA/SM.
template<int EPI, typename TO>
__global__ void __launch_bounds__(256, 2)
gemm_h(const __half* __restrict__ A, const __half* __restrict__ Bm,
       TO* __restrict__ Cc, const float* __restrict__ bias,
       const float* __restrict__ res, int M, int Nn, int K)
{
    constexpr int BM = 128, BN = 128, BK = 64, ST = 3;
    constexpr int STAGE_H = BM * BK;
    extern __shared__ char smc[];
    __half* As = (__half*)smc;
    __half* Bs = As + ST * STAGE_H;

    const int tid  = threadIdx.x;
    const int warp = tid >> 5, lane = tid & 31;
    const int g    = lane >> 2, qd = lane & 3;
    const int wM   = warp >> 2, wN = warp & 3;
    const int bM   = blockIdx.y * BM, bN = blockIdx.x * BN;

    const uint32_t as_u = smem_u32(As);
    const uint32_t bs_u = smem_u32(Bs);

    const int l7 = lane & 7;
    int aRow[4], bRow[2];
    #pragma unroll
    for (int i = 0; i < 4; i++)
        aRow[i] = wM * 64 + i * 16 + l7 + ((lane >> 3) & 1) * 8;
    const int cA = (lane >> 4) & 1;
    #pragma unroll
    for (int jj = 0; jj < 2; jj++)
        bRow[jj] = wN * 32 + jj * 16 + l7 + ((lane >> 4) & 1) * 8;
    const int cB = (lane >> 3) & 1;

    float acc[4][4][4];
    #pragma unroll
    for (int i = 0; i < 4; i++)
        #pragma unroll
        for (int j = 0; j < 4; j++)
            #pragma unroll
            for (int e = 0; e < 4; e++) acc[i][j][e] = 0.f;

    const int KT = K / BK;

    auto load_stage = [&](int s, int k0) {
        #pragma unroll
        for (int j = 0; j < 4; j++) {
            int f = tid + j * 256;
            int r = f >> 3, q = f & 7;
            uint32_t off = (uint32_t)(r * 128 + ((q ^ (r & 7)) * 16));
            cp16(as_u + (uint32_t)s * 16384u + off,
                 A  + (size_t)(bM + r) * K + k0 + q * 8);
            cp16(bs_u + (uint32_t)s * 16384u + off,
                 Bm + (size_t)(bN + r) * K + k0 + q * 8);
        }
        cp_commit();
    };

    #pragma unroll
    for (int s = 0; s < ST - 1; s++) load_stage(s, s * BK);

    for (int t = 0; t < KT; t++) {
        cp_wait<ST - 2>();
        __syncthreads();

        int tn = t + ST - 1;
        if (tn < KT) load_stage(tn % ST, tn * BK);
        else         cp_commit();

        const uint32_t a_st = as_u + (uint32_t)(t % ST) * 16384u;
        const uint32_t b_st = bs_u + (uint32_t)(t % ST) * 16384u;

        #pragma unroll
        for (int kk = 0; kk < 4; kk++) {
            const int chA = 2 * kk + cA;
            const int chB = 2 * kk + cB;
            uint32_t bf[2][4];
            #pragma unroll
            for (int jj = 0; jj < 2; jj++)
                ldsm4(bf[jj], b_st + (uint32_t)(bRow[jj] * 128
                                 + ((chB ^ (bRow[jj] & 7)) * 16)));
            #pragma unroll
            for (int i = 0; i < 4; i++) {
                uint32_t af[4];
                ldsm4(af, a_st + (uint32_t)(aRow[i] * 128
                               + ((chA ^ (aRow[i] & 7)) * 16)));
                #pragma unroll
                for (int j = 0; j < 4; j++)
                    mma_f16(acc[i][j], af, &bf[j >> 1][(j & 1) * 2]);
            }
        }
    }

    #pragma unroll
    for (int i = 0; i < 4; i++) {
        #pragma unroll
        for (int j = 0; j < 4; j++) {
            int r0 = bM + wM * 64 + i * 16 + g;
            int c0 = bN + wN * 32 + j * 8 + qd * 2;
            #pragma unroll
            for (int hh = 0; hh < 2; hh++) {
                int r = r0 + hh * 8;
                float v0 = acc[i][j][hh * 2 + 0];
                float v1 = acc[i][j][hh * 2 + 1];
                if (EPI >= 1) { v0 += bias[c0]; v1 += bias[c0 + 1]; }
                if (EPI == 1) {
                    v0 = 0.5f * v0 * (1.f + erff(v0 * 0.70710678118654752f));
                    v1 = 0.5f * v1 * (1.f + erff(v1 * 0.70710678118654752f));
                }
                if (EPI == 2) {
                    const float2 rr = *(const float2*)(res + (size_t)r * Nn + c0);
                    v0 += rr.x; v1 += rr.y;
                }
                store2(Cc + (size_t)r * Nn + c0, v0, v1);
            }
        }
    }
}

// ---------------- FP16 tensor-core flash attention (persistent) --------------
// 128-key prefetch pairs (2x64-row buffers), 2 compute passes per barrier.
// Register-resident P, exp2 softmax via ex2.approx.f16x2.
#define AGRID 296
__global__ void __launch_bounds__(256, 2)
attn_mma(const __half* __restrict__ qkv, __half* __restrict__ o)
{
    // dynamic smem: Ks 4x8KB | Vs 4x8KB | Qs 128x72 halves (18KB) = 82KB
    extern __shared__ char smc[];
    const uint32_t sb   = smem_u32(smc);
    const uint32_t ks_u = sb;
    const uint32_t vs_u = sb + 32768;
    const uint32_t qs_u = sb + 65536;
    __half* Qs = (__half*)(smc + 65536);

    const int tid  = threadIdx.x;
    const int warp = tid >> 5, lane = tid & 31;
    const int l7   = lane & 7;
    const int g    = lane >> 2, qd = lane & 3;
    const int wr   = warp * 16;
    const int RS = 3 * C_;
    const int NP = N_ / 128;             // key pairs (8)

    const int kRow = l7 + ((lane >> 4) & 1) * 8;
    const int kCh  = (lane >> 3) & 1;
    const int vRow = l7 + ((lane >> 3) & 1) * 8;
    const int vCh  = (lane >> 4) & 1;
    const int qrow = wr + l7 + ((lane >> 3) & 1) * 8;
    const int qch  = (lane >> 4) & 1;
    const __half2 sc = __float2half2_rn(0.125f * 1.44269504088896340736f);

    for (int item = blockIdx.x; item < 512; item += AGRID) {
        const int b  = item >> 7;
        const int h  = (item >> 3) & 15;
        const int q0 = (item & 7) * 128;

        // prefetch 128 keys (one pair) into buffers (p&1)*2 and (p&1)*2+1
        auto prefetch = [&](int p) {
            #pragma unroll
            for (int e = 0; e < 4; e++) {
                int f = tid + e * 256;           // 0..1023
                int r = f >> 3, q = f & 7;       // r: 0..127
                uint32_t buf = (uint32_t)((p & 1) * 2 + (r >> 6));
                uint32_t off = buf * 8192u
                             + (uint32_t)((r & 63) * 128 + ((q ^ (r & 7)) * 16));
                const __half* base = qkv + (size_t)(b * N_ + p * 128 + r) * RS
                                   + h * DH + q * 8;
                cp16(ks_u + off, base + C_);
                cp16(vs_u + off, base + 2 * C_);
            }
            cp_commit();
        };
        prefetch(0);

        for (int i = tid; i < 128 * 8; i += 256) {
            int r = i >> 3, c = i & 7;
            *(uint4*)&Qs[r * 72 + c * 8] =
                *(const uint4*)(qkv + (size_t)(b * N_ + q0 + r) * RS + h * DH + c * 8);
        }
        __syncthreads();

        uint32_t qf[4][4];
        #pragma unroll
        for (int kk = 0; kk < 4; kk++) {
            ldsm4(qf[kk], qs_u + (uint32_t)(qrow * 144 + (2 * kk + qch) * 16));
            #pragma unroll
            for (int e = 0; e < 4; e++) {
                __half2 t = __hmul2(*(__half2*)&qf[kk][e], sc);
                qf[kk][e] = *(uint32_t*)&t;
            }
        }

        float oacc[8][4];
        #pragma unroll
        for (int nb = 0; nb < 8; nb++)
            #pragma unroll
            for (int e = 0; e < 4; e++) oacc[nb][e] = 0.f;
        float m0 = -1e30f, m1 = -1e30f, l0 = 0.f, l1 = 0.f;

        for (int p = 0; p < NP; p++) {
            cp_wait<0>();
            __syncthreads();
            if (p + 1 < NP) prefetch(p + 1);

            #pragma unroll
            for (int hb = 0; hb < 2; hb++) {
                const uint32_t K_ = ks_u + (uint32_t)(((p & 1) * 2 + hb) * 8192);
                const uint32_t V_ = vs_u + (uint32_t)(((p & 1) * 2 + hb) * 8192);

                // S = (Q * 0.125 * log2e) @ K^T
                float sacc[8][4];
                #pragma unroll
                for (int nb = 0; nb < 8; nb++)
                    #pragma unroll
                    for (int e = 0; e < 4; e++) sacc[nb][e] = 0.f;
                #pragma unroll
                for (int kk = 0; kk < 4; kk++) {
                    uint32_t bf[4][4];
                    #pragma unroll
                    for (int pp = 0; pp < 4; pp++) {
                        int row = pp * 16 + kRow;
                        ldsm4(bf[pp], K_ + (uint32_t)(row * 128
                                    + (((2 * kk + kCh) ^ (row & 7)) * 16)));
                    }
                    #pragma unroll
                    for (int nb = 0; nb < 8; nb++)
                        mma_f16(sacc[nb], qf[kk], &bf[nb >> 1][(nb & 1) * 2]);
                }

                // online softmax (exp2 domain), exp in f16x2
                float mx0 = -1e30f, mx1 = -1e30f;
                #pragma unroll
                for (int nb = 0; nb < 8; nb++) {
                    mx0 = fmaxf(mx0, fmaxf(sacc[nb][0], sacc[nb][1]));
                    mx1 = fmaxf(mx1, fmaxf(sacc[nb][2], sacc[nb][3]));
                }
                mx0 = fmaxf(mx0, __shfl_xor_sync(0xffffffffu, mx0, 1));
                mx0 = fmaxf(mx0, __shfl_xor_sync(0xffffffffu, mx0, 2));
                mx1 = fmaxf(mx1, __shfl_xor_sync(0xffffffffu, mx1, 1));
                mx1 = fmaxf(mx1, __shfl_xor_sync(0xffffffffu, mx1, 2));

                float mn0 = fmaxf(m0, mx0), mn1 = fmaxf(m1, mx1);
                float cc0 = exp2f(m0 - mn0), cc1 = exp2f(m1 - mn1);
                float s0 = 0.f, s1 = 0.f;
                uint32_t pa[8], pb[8];
                #pragma unroll
                for (int nb = 0; nb < 8; nb++) {
                    __half2 da = __floats2half2_rn(sacc[nb][0] - mn0, sacc[nb][1] - mn0);
                    __half2 db = __floats2half2_rn(sacc[nb][2] - mn1, sacc[nb][3] - mn1);
                    pa[nb] = h2exp2_(*(uint32_t*)&da);
                    pb[nb] = h2exp2_(*(uint32_t*)&db);
                    float2 fa = __half22float2(*(__half2*)&pa[nb]);
                    float2 fb = __half22float2(*(__half2*)&pb[nb]);
                    s0 += fa.x + fa.y;
                    s1 += fb.x + fb.y;
                }
                s0 += __shfl_xor_sync(0xffffffffu, s0, 1);
                s0 += __shfl_xor_sync(0xffffffffu, s0, 2);
                s1 += __shfl_xor_sync(0xffffffffu, s1, 1);
                s1 += __shfl_xor_sync(0xffffffffu, s1, 2);
                l0 = l0 * cc0 + s0;  l1 = l1 * cc1 + s1;
                m0 = mn0;  m1 = mn1;
                #pragma unroll
                for (int nb = 0; nb < 8; nb++) {
                    oacc[nb][0] *= cc0; oacc[nb][1] *= cc0;
                    oacc[nb][2] *= cc1; oacc[nb][3] *= cc1;
                }

                // O += P @ V
                #pragma unroll
                for (int jc = 0; jc < 4; jc++) {
                    uint32_t af[4];
                    af[0] = pa[2 * jc];     af[1] = pb[2 * jc];
                    af[2] = pa[2 * jc + 1]; af[3] = pb[2 * jc + 1];
                    uint32_t bf[4][4];
                    #pragma unroll
                    for (int pp = 0; pp < 4; pp++) {
                        int row = jc * 16 + vRow;
                        ldsm4t(bf[pp], V_ + (uint32_t)(row * 128
                                     + (((2 * pp + vCh) ^ (row & 7)) * 16)));
                    }
                    #pragma unroll
                    for (int nb = 0; nb < 8; nb++)
                        mma_f16(oacc[nb], af, &bf[nb >> 1][(nb & 1) * 2]);
                }
            }
        }

        float i0 = 1.f / l0, i1 = 1.f / l1;
        __half* op0 = o + (size_t)(b * N_ + q0 + wr + g    ) * C_ + h * DH;
        __half* op1 = o + (size_t)(b * N_ + q0 + wr + g + 8) * C_ + h * DH;
        #pragma unroll
        for (int nb = 0; nb < 8; nb++) {
            int c = nb * 8 + qd * 2;
            *(__half2*)(op0 + c) = __floats2half2_rn(oacc[nb][0] * i0, oacc[nb][1] * i0);
            *(__half2*)(op1 + c) = __floats2half2_rn(oacc[nb][2] * i1, oacc[nb][3] * i1);
        }
    }
}

// ---------------- launch ----------------------------------------------------
extern "C" void kernel_launch(void* const* d_in, const int* in_sizes, int n_in,
                              void* d_out, int out_size)
{
    const float* x      = (const float*)d_in[0];
    const float* qkv_w  = (const float*)d_in[1];
    const float* proj_w = (const float*)d_in[2];
    const float* proj_b = (const float*)d_in[3];
    const float* fc1_w  = (const float*)d_in[4];
    const float* fc1_b  = (const float*)d_in[5];
    const float* fc2_w  = (const float*)d_in[6];
    const float* fc2_b  = (const float*)d_in[7];
    const float* ln1_g  = (const float*)d_in[8];
    const float* ln1_b  = (const float*)d_in[9];
    const float* ln2_g  = (const float*)d_in[10];
    const float* ln2_b  = (const float*)d_in[11];
    const float* lnh_g  = (const float*)d_in[12];
    const float* lnh_b  = (const float*)d_in[13];
    float* out = (float*)d_out;

    __half *h, *qkv, *o, *u, *w;
    float *x1;
    cudaGetSymbolAddress((void**)&h,   g_h);
    cudaGetSymbolAddress((void**)&qkv, g_qkv);
    cudaGetSymbolAddress((void**)&o,   g_o);
    cudaGetSymbolAddress((void**)&x1,  g_x1);
    cudaGetSymbolAddress((void**)&u,   g_u);
    cudaGetSymbolAddress((void**)&w,   g_w);
    __half* wq = w;
    __half* wp = wq + 3*C_*C_;
    __half* w1 = wp + C_*C_;
    __half* w2 = w1 + DHID*C_;

    const int SMEM  = 3 * 128 * 64 * 2 * 2;          // 96 KB (GEMM)
    const int ASMEM = 32768 + 32768 + 128 * 72 * 2;  // 82.5 KB (attention)
    cudaFuncSetAttribute(gemm_h<0,__half>, cudaFuncAttributeMaxDynamicSharedMemorySize, SMEM);
    cudaFuncSetAttribute(gemm_h<1,__half>, cudaFuncAttributeMaxDynamicSharedMemorySize, SMEM);
    cudaFuncSetAttribute(gemm_h<2,float >, cudaFuncAttributeMaxDynamicSharedMemorySize, SMEM);
    cudaFuncSetAttribute(attn_mma,         cudaFuncAttributeMaxDynamicSharedMemorySize, ASMEM);

    // fused weight conversion fp32 -> fp16 (one launch)
    {
        const int total4 = (3*C_*C_ + C_*C_ + DHID*C_ + C_*DHID) / 4;
        cvt_all_kernel<<<(total4 + 255)/256, 256>>>(qkv_w, proj_w, fc1_w, fc2_w, w);
    }

    // --- attention sublayer ---
    ln_warp<<<R_/8, 256>>>(x, ln1_g, ln1_b, h);
    gemm_h<0,__half><<<dim3(3*C_/128, R_/128), 256, SMEM>>>(h, wq, qkv,
                                                   nullptr, nullptr, R_, 3*C_, C_);
    attn_mma<<<AGRID, 256, ASMEM>>>(qkv, o);
    gemm_h<2,float><<<dim3(C_/128, R_/128), 256, SMEM>>>(o, wp, x1,
                                                   proj_b, x, R_, C_, C_);

    // --- MLP sublayer ---
    ln_warp<<<R_/8, 256>>>(x1, ln2_g, ln2_b, h);
    gemm_h<1,__half><<<dim3(DHID/128, R_/128), 256, SMEM>>>(h, w1, u,
                                                   fc1_b, nullptr, R_, DHID, C_);
    ln_h<DHID><<<R_, 256>>>(u, lnh_g, lnh_b, u);
    gemm_h<2,float><<<dim3(C_/128, R_/128), 256, SMEM>>>(u, w2, out,
                                                   fc2_b, x1, R_, C_, DHID);
}